// round 11
// baseline (speedup 1.0000x reference)
#include <cuda_runtime.h>
#include <cuda_fp16.h>

#define NUSER 100000
#define NITEM 50000
#define NEDGE 2000000
#define DIM   64
#define NLAYERS 3

// ---------------- scratch (device globals) ----------------
__device__ __half g_pu[NUSER * DIM];    // pre-scaled user operand
__device__ __half g_pi[NITEM * DIM];    // pre-scaled item operand
__device__ __half g_au[NUSER * DIM];    // phase-A out, user rows (d_u^-1 * R(pi))
__device__ __half g_ai[NITEM * DIM];    // phase-A out, item rows (d_i^-1 * RT(pu))
__device__ __half g_hcu0[NUSER * DIM];  // layer-0 contribution d_u^-1/2 * S_0
__device__ __half g_hcu1[NUSER * DIM];  // layer-1 contribution
__device__ __half g_hci0[NITEM * DIM];
__device__ __half g_hci1[NITEM * DIM];
__device__ int    g_cnt[NUSER + NITEM];
__device__ int    g_rowptr_u[NUSER + 1];
__device__ int    g_rowptr_i[NITEM + 1];
__device__ int    g_cur_u[NUSER];
__device__ int    g_cur_i[NITEM];
__device__ int    g_cols_u[NEDGE];
__device__ int    g_cols_i[NEDGE];
__device__ float  g_nu_inv[NUSER];
__device__ float  g_nu_is [NUSER];
__device__ float  g_ni_inv[NITEM];
__device__ float  g_ni_is [NITEM];

// ---------------- helpers ----------------
__device__ __forceinline__ uint2 pack4h(float4 v) {
    __half2 a = __floats2half2_rn(v.x, v.y);
    __half2 b = __floats2half2_rn(v.z, v.w);
    uint2 r;
    r.x = *reinterpret_cast<unsigned*>(&a);
    r.y = *reinterpret_cast<unsigned*>(&b);
    return r;
}

__device__ __forceinline__ float4 unpack4h(uint2 v) {
    __half2 h0 = *reinterpret_cast<__half2*>(&v.x);
    __half2 h1 = *reinterpret_cast<__half2*>(&v.y);
    float2 f0 = __half22float2(h0);
    float2 f1 = __half22float2(h1);
    return make_float4(f0.x, f0.y, f1.x, f1.y);
}

// gather load with no L1 allocation: rows are touched once per wavefront with
// ~1% L1 hit probability (19MB footprint vs 228KB L1) — filling L1 is pure churn.
__device__ __forceinline__ uint2 ldg_na(const uint2* p) {
    uint2 v;
    asm("ld.global.nc.L1::no_allocate.v2.u32 {%0,%1}, [%2];"
        : "=r"(v.x), "=r"(v.y) : "l"(p));
    return v;
}

// gather-add over one CSR row: 16 lanes per row, 8B (4 halves) per lane.
// fp32 accumulation; moderate unroll (MLP_p1 ~ 4 avoids cross-CTA L1tex spread).
__device__ __forceinline__ float4 gather_row(const uint2* __restrict__ src,
                                             const int*   __restrict__ cols,
                                             int beg, int end, int c, unsigned hmask) {
    float4 acc = make_float4(0.f, 0.f, 0.f, 0.f);
    for (int base = beg; base < end; base += 16) {
        int myi = base + c;
        int mycol = (myi < end) ? __ldg(cols + myi) : 0;
        int cnt = min(16, end - base);
        #pragma unroll 4
        for (int j = 0; j < cnt; ++j) {
            int col = __shfl_sync(hmask, mycol, j, 16);
            uint2 v = ldg_na(src + col * 16 + c);
            float4 f = unpack4h(v);
            acc.x += f.x; acc.y += f.y; acc.z += f.z; acc.w += f.w;
        }
    }
    return acc;
}

// ---------------- CSR build ----------------
__global__ void hist_degrees(const int* __restrict__ u_idx,
                             const int* __restrict__ i_idx,
                             int* __restrict__ cnt) {
    int t = blockIdx.x * blockDim.x + threadIdx.x;
    if (t >= NEDGE) return;
    atomicAdd(cnt + __ldg(u_idx + t), 1);
    atomicAdd(cnt + NUSER + __ldg(i_idx + t), 1);
}

// One kernel, 2 blocks of 1024: block 0 = users, block 1 = items.
__global__ void __launch_bounds__(1024)
fused_scan(const int* __restrict__ cnt_all,
           int* __restrict__ rp_u, int* __restrict__ rp_i,
           int* __restrict__ cur_u, int* __restrict__ cur_i,
           float* __restrict__ nu_inv, float* __restrict__ nu_is,
           float* __restrict__ ni_inv, float* __restrict__ ni_is) {
    const bool users = (blockIdx.x == 0);
    const int n = users ? NUSER : NITEM;
    const int* __restrict__ cnt = users ? cnt_all : (cnt_all + NUSER);
    int* __restrict__ rp  = users ? rp_u  : rp_i;
    int* __restrict__ cur = users ? cur_u : cur_i;
    float* __restrict__ inv = users ? nu_inv : ni_inv;
    float* __restrict__ isq = users ? nu_is  : ni_is;

    const int per = (n + 1023) / 1024;
    int beg = threadIdx.x * per;
    int end = min(n, beg + per);

    int s = 0;
    for (int e = beg; e < end; ++e) s += __ldg(cnt + e);

    __shared__ int sh[1024];
    sh[threadIdx.x] = s;
    __syncthreads();
    for (int off = 1; off < 1024; off <<= 1) {
        int t = (threadIdx.x >= off) ? sh[threadIdx.x - off] : 0;
        __syncthreads();
        sh[threadIdx.x] += t;
        __syncthreads();
    }
    int run = sh[threadIdx.x] - s;   // exclusive prefix

    for (int e = beg; e < end; ++e) {
        int c = __ldg(cnt + e);
        rp[e]  = run;
        cur[e] = run;
        float d = c ? (float)c : 1.0f;
        inv[e] = 1.0f / d;
        isq[e] = rsqrtf(d);
        run += c;
    }
    if (threadIdx.x == 0) rp[n] = NEDGE;
}

__global__ void fill_csr(const int* __restrict__ u_idx, const int* __restrict__ i_idx,
                         int* __restrict__ cur_u, int* __restrict__ cur_i,
                         int* __restrict__ cols_u, int* __restrict__ cols_i) {
    int e = blockIdx.x * blockDim.x + threadIdx.x;
    if (e >= NEDGE) return;
    int u = __ldg(u_idx + e);
    int i = __ldg(i_idx + e);
    cols_u[atomicAdd(cur_u + u, 1)] = i;
    cols_i[atomicAdd(cur_i + i, 1)] = u;
}

// ---------------- prescale: P = d^-1/2 * emb  (fp32 -> fp16) ----------------
__global__ void prescale(const float4* __restrict__ ue, const float4* __restrict__ ie,
                         const float* __restrict__ nu_is, const float* __restrict__ ni_is,
                         uint2* __restrict__ pu, uint2* __restrict__ pi) {
    int t = blockIdx.x * blockDim.x + threadIdx.x;
    if (t >= (NUSER + NITEM) * 16) return;
    if (t < NUSER * 16) {
        float s = __ldg(nu_is + (t >> 4));
        float4 v = __ldg(ue + t);
        v.x *= s; v.y *= s; v.z *= s; v.w *= s;
        pu[t] = pack4h(v);
    } else {
        int tt = t - NUSER * 16;
        float s = __ldg(ni_is + (tt >> 4));
        float4 v = __ldg(ie + tt);
        v.x *= s; v.y *= s; v.z *= s; v.w *= s;
        pi[tt] = pack4h(v);
    }
}

// ---------------- phase A: ai = d_i^-1 * RT(pu);  au = d_u^-1 * R(pi) ----------------
__global__ void __launch_bounds__(256)
phaseA(const uint2* __restrict__ pu, const uint2* __restrict__ pi,
       const int* __restrict__ rp_i, const int* __restrict__ cols_i,
       const int* __restrict__ rp_u, const int* __restrict__ cols_u,
       const float* __restrict__ ni_inv, const float* __restrict__ nu_inv,
       uint2* __restrict__ ai, uint2* __restrict__ au) {
    int t = blockIdx.x * blockDim.x + threadIdx.x;
    int r = t >> 4;
    if (r >= NITEM + NUSER) return;
    int c = t & 15;
    unsigned hmask = 0xFFFFu << (threadIdx.x & 16);
    if (r < NITEM) {
        float4 acc = gather_row(pu, cols_i, __ldg(rp_i + r), __ldg(rp_i + r + 1), c, hmask);
        float s = __ldg(ni_inv + r);
        acc.x *= s; acc.y *= s; acc.z *= s; acc.w *= s;
        ai[r * 16 + c] = pack4h(acc);
    } else {
        int u = r - NITEM;
        float4 acc = gather_row(pi, cols_u, __ldg(rp_u + u), __ldg(rp_u + u + 1), c, hmask);
        float s = __ldg(nu_inv + u);
        acc.x *= s; acc.y *= s; acc.z *= s; acc.w *= s;
        au[u * 16 + c] = pack4h(acc);
    }
}

// ---------------- phase B (layers 0..n-2): contribution + next operand ----------------
__global__ void __launch_bounds__(256)
phaseB_mid(const uint2* __restrict__ ai, const uint2* __restrict__ au,
           const int* __restrict__ rp_u, const int* __restrict__ cols_u,
           const int* __restrict__ rp_i, const int* __restrict__ cols_i,
           const float* __restrict__ nu_is, const float* __restrict__ nu_inv,
           const float* __restrict__ ni_is, const float* __restrict__ ni_inv,
           uint2* __restrict__ hc_u, uint2* __restrict__ hc_i,
           uint2* __restrict__ pu, uint2* __restrict__ pi) {
    int t = blockIdx.x * blockDim.x + threadIdx.x;
    int r = t >> 4;
    if (r >= NITEM + NUSER) return;
    int c = t & 15;
    unsigned hmask = 0xFFFFu << (threadIdx.x & 16);
    if (r < NUSER) {
        int idx = r * 16 + c;
        float4 S = gather_row(ai, cols_u, __ldg(rp_u + r), __ldg(rp_u + r + 1), c, hmask);
        float sis = __ldg(nu_is + r);
        float si  = __ldg(nu_inv + r);
        float4 h; h.x = sis * S.x; h.y = sis * S.y; h.z = sis * S.z; h.w = sis * S.w;
        float4 p; p.x = si  * S.x; p.y = si  * S.y; p.z = si  * S.z; p.w = si  * S.w;
        hc_u[idx] = pack4h(h);
        pu[idx]   = pack4h(p);
    } else {
        int i = r - NUSER;
        int idx = i * 16 + c;
        float4 S = gather_row(au, cols_i, __ldg(rp_i + i), __ldg(rp_i + i + 1), c, hmask);
        float sis = __ldg(ni_is + i);
        float si  = __ldg(ni_inv + i);
        float4 h; h.x = sis * S.x; h.y = sis * S.y; h.z = sis * S.z; h.w = sis * S.w;
        float4 p; p.x = si  * S.x; p.y = si  * S.y; p.z = si  * S.z; p.w = si  * S.w;
        hc_i[idx] = pack4h(h);
        pi[idx]   = pack4h(p);
    }
}

// ---------------- phase B (last layer): out = 0.25*(emb + c0 + c1 + d^-1/2 * S) ----------------
__global__ void __launch_bounds__(256)
phaseB_last(const uint2* __restrict__ ai, const uint2* __restrict__ au,
            const int* __restrict__ rp_u, const int* __restrict__ cols_u,
            const int* __restrict__ rp_i, const int* __restrict__ cols_i,
            const float* __restrict__ nu_is, const float* __restrict__ ni_is,
            const float4* __restrict__ emb_u, const float4* __restrict__ emb_i,
            const uint2* __restrict__ hcu0, const uint2* __restrict__ hcu1,
            const uint2* __restrict__ hci0, const uint2* __restrict__ hci1,
            float4* __restrict__ sum_u, float4* __restrict__ sum_i) {
    int t = blockIdx.x * blockDim.x + threadIdx.x;
    int r = t >> 4;
    if (r >= NITEM + NUSER) return;
    int c = t & 15;
    unsigned hmask = 0xFFFFu << (threadIdx.x & 16);
    const float k = 1.0f / (NLAYERS + 1);
    if (r < NUSER) {
        int idx = r * 16 + c;
        float4 S = gather_row(ai, cols_u, __ldg(rp_u + r), __ldg(rp_u + r + 1), c, hmask);
        float sis = __ldg(nu_is + r);
        float4 e  = __ldg(emb_u + idx);
        float4 c0 = unpack4h(__ldg(hcu0 + idx));
        float4 c1 = unpack4h(__ldg(hcu1 + idx));
        float4 o;
        o.x = k * (e.x + c0.x + c1.x + sis * S.x);
        o.y = k * (e.y + c0.y + c1.y + sis * S.y);
        o.z = k * (e.z + c0.z + c1.z + sis * S.z);
        o.w = k * (e.w + c0.w + c1.w + sis * S.w);
        sum_u[idx] = o;
    } else {
        int i = r - NUSER;
        int idx = i * 16 + c;
        float4 S = gather_row(au, cols_i, __ldg(rp_i + i), __ldg(rp_i + i + 1), c, hmask);
        float sis = __ldg(ni_is + i);
        float4 e  = __ldg(emb_i + idx);
        float4 c0 = unpack4h(__ldg(hci0 + idx));
        float4 c1 = unpack4h(__ldg(hci1 + idx));
        float4 o;
        o.x = k * (e.x + c0.x + c1.x + sis * S.x);
        o.y = k * (e.y + c0.y + c1.y + sis * S.y);
        o.z = k * (e.z + c0.z + c1.z + sis * S.z);
        o.w = k * (e.w + c0.w + c1.w + sis * S.w);
        sum_i[idx] = o;
    }
}

// ---------------- launch ----------------
extern "C" void kernel_launch(void* const* d_in, const int* in_sizes, int n_in,
                              void* d_out, int out_size) {
    const float* user_emb = (const float*)d_in[0];
    const float* item_emb = (const float*)d_in[1];
    const int*   u_idx    = (const int*)d_in[2];
    const int*   i_idx    = (const int*)d_in[3];
    float* out = (float*)d_out;
    float* sum_u = out;
    float* sum_i = out + NUSER * DIM;

    __half *p_pu, *p_pi, *p_au, *p_ai, *p_hcu0, *p_hcu1, *p_hci0, *p_hci1;
    float *p_nu_inv, *p_nu_is, *p_ni_inv, *p_ni_is;
    int *p_cnt, *p_rp_u, *p_rp_i, *p_cur_u, *p_cur_i, *p_cols_u, *p_cols_i;
    cudaGetSymbolAddress((void**)&p_pu, g_pu);
    cudaGetSymbolAddress((void**)&p_pi, g_pi);
    cudaGetSymbolAddress((void**)&p_au, g_au);
    cudaGetSymbolAddress((void**)&p_ai, g_ai);
    cudaGetSymbolAddress((void**)&p_hcu0, g_hcu0);
    cudaGetSymbolAddress((void**)&p_hcu1, g_hcu1);
    cudaGetSymbolAddress((void**)&p_hci0, g_hci0);
    cudaGetSymbolAddress((void**)&p_hci1, g_hci1);
    cudaGetSymbolAddress((void**)&p_nu_inv, g_nu_inv);
    cudaGetSymbolAddress((void**)&p_nu_is,  g_nu_is);
    cudaGetSymbolAddress((void**)&p_ni_inv, g_ni_inv);
    cudaGetSymbolAddress((void**)&p_ni_is,  g_ni_is);
    cudaGetSymbolAddress((void**)&p_cnt,    g_cnt);
    cudaGetSymbolAddress((void**)&p_rp_u,   g_rowptr_u);
    cudaGetSymbolAddress((void**)&p_rp_i,   g_rowptr_i);
    cudaGetSymbolAddress((void**)&p_cur_u,  g_cur_u);
    cudaGetSymbolAddress((void**)&p_cur_i,  g_cur_i);
    cudaGetSymbolAddress((void**)&p_cols_u, g_cols_u);
    cudaGetSymbolAddress((void**)&p_cols_i, g_cols_i);

    const int TB = 256;
    const int EDGE_BLKS = (NEDGE + TB - 1) / TB;
    const int ALL_BLKS  = ((NUSER + NITEM) * 16 + TB - 1) / TB;

    // ---- CSR build + norms (5-node prologue) ----
    cudaMemsetAsync(p_cnt, 0, (NUSER + NITEM) * sizeof(int), 0);
    hist_degrees<<<EDGE_BLKS, TB>>>(u_idx, i_idx, p_cnt);
    fused_scan<<<2, 1024>>>(p_cnt, p_rp_u, p_rp_i, p_cur_u, p_cur_i,
                            p_nu_inv, p_nu_is, p_ni_inv, p_ni_is);
    fill_csr<<<EDGE_BLKS, TB>>>(u_idx, i_idx, p_cur_u, p_cur_i, p_cols_u, p_cols_i);

    // ---- initial pre-scaled operands ----
    prescale<<<ALL_BLKS, TB>>>((const float4*)user_emb, (const float4*)item_emb,
                               p_nu_is, p_ni_is, (uint2*)p_pu, (uint2*)p_pi);

    // ---- layers ----
    uint2* HCU[2] = { (uint2*)p_hcu0, (uint2*)p_hcu1 };
    uint2* HCI[2] = { (uint2*)p_hci0, (uint2*)p_hci1 };
    for (int layer = 0; layer < NLAYERS; ++layer) {
        phaseA<<<ALL_BLKS, TB>>>((const uint2*)p_pu, (const uint2*)p_pi,
                                 p_rp_i, p_cols_i, p_rp_u, p_cols_u,
                                 p_ni_inv, p_nu_inv, (uint2*)p_ai, (uint2*)p_au);
        if (layer < NLAYERS - 1) {
            phaseB_mid<<<ALL_BLKS, TB>>>((const uint2*)p_ai, (const uint2*)p_au,
                                         p_rp_u, p_cols_u, p_rp_i, p_cols_i,
                                         p_nu_is, p_nu_inv, p_ni_is, p_ni_inv,
                                         HCU[layer], HCI[layer],
                                         (uint2*)p_pu, (uint2*)p_pi);
        } else {
            phaseB_last<<<ALL_BLKS, TB>>>((const uint2*)p_ai, (const uint2*)p_au,
                                          p_rp_u, p_cols_u, p_rp_i, p_cols_i,
                                          p_nu_is, p_ni_is,
                                          (const float4*)user_emb, (const float4*)item_emb,
                                          (const uint2*)p_hcu0, (const uint2*)p_hcu1,
                                          (const uint2*)p_hci0, (const uint2*)p_hci1,
                                          (float4*)sum_u, (float4*)sum_i);
        }
    }
}

// round 12
// speedup vs baseline: 1.5795x; 1.5795x over previous
#include <cuda_runtime.h>
#include <cuda_fp16.h>

#define NUSER 100000
#define NITEM 50000
#define NEDGE 2000000
#define DIM   64
#define NLAYERS 3

// ---------------- scratch (device globals) ----------------
__device__ __half g_pu[NUSER * DIM];    // pre-scaled user operand
__device__ __half g_pi[NITEM * DIM];    // pre-scaled item operand
__device__ __half g_au[NUSER * DIM];    // phase-A out, user rows (d_u^-1 * R(pi))
__device__ __half g_ai[NITEM * DIM];    // phase-A out, item rows (d_i^-1 * RT(pu))
__device__ __half g_hcu0[NUSER * DIM];  // layer-0 contribution d_u^-1/2 * S_0
__device__ __half g_hcu1[NUSER * DIM];  // layer-1 contribution
__device__ __half g_hci0[NITEM * DIM];
__device__ __half g_hci1[NITEM * DIM];
__device__ int    g_cnt[NUSER + NITEM];
__device__ int    g_rowptr_u[NUSER + 1];
__device__ int    g_rowptr_i[NITEM + 1];
__device__ int    g_cur_u[NUSER];
__device__ int    g_cur_i[NITEM];
__device__ int    g_cols_u[NEDGE];
__device__ int    g_cols_i[NEDGE];
__device__ float  g_nu_inv[NUSER];
__device__ float  g_nu_is [NUSER];
__device__ float  g_ni_inv[NITEM];
__device__ float  g_ni_is [NITEM];

// ---------------- helpers ----------------
__device__ __forceinline__ uint2 pack4h(float4 v) {
    __half2 a = __floats2half2_rn(v.x, v.y);
    __half2 b = __floats2half2_rn(v.z, v.w);
    uint2 r;
    r.x = *reinterpret_cast<unsigned*>(&a);
    r.y = *reinterpret_cast<unsigned*>(&b);
    return r;
}

__device__ __forceinline__ float4 unpack4h(uint2 v) {
    __half2 h0 = *reinterpret_cast<__half2*>(&v.x);
    __half2 h1 = *reinterpret_cast<__half2*>(&v.y);
    float2 f0 = __half22float2(h0);
    float2 f1 = __half22float2(h1);
    return make_float4(f0.x, f0.y, f1.x, f1.y);
}

// gather-add over one CSR row: 16 lanes per row, 8B (4 halves) per lane.
// fp32 accumulation; moderate unroll (MLP_p1 ~ 4 avoids cross-CTA L1tex spread).
// NOTE: plain __ldg (L1-allocating) — source rows have deg~20-40x temporal reuse;
// L1::no_allocate measured a ~25% clock-normalized regression (round 11).
__device__ __forceinline__ float4 gather_row(const uint2* __restrict__ src,
                                             const int*   __restrict__ cols,
                                             int beg, int end, int c, unsigned hmask) {
    float4 acc = make_float4(0.f, 0.f, 0.f, 0.f);
    for (int base = beg; base < end; base += 16) {
        int myi = base + c;
        int mycol = (myi < end) ? __ldg(cols + myi) : 0;
        int cnt = min(16, end - base);
        #pragma unroll 4
        for (int j = 0; j < cnt; ++j) {
            int col = __shfl_sync(hmask, mycol, j, 16);
            uint2 v = __ldg(src + col * 16 + c);
            float4 f = unpack4h(v);
            acc.x += f.x; acc.y += f.y; acc.z += f.z; acc.w += f.w;
        }
    }
    return acc;
}

// ---------------- CSR build ----------------
__global__ void hist_degrees(const int* __restrict__ u_idx,
                             const int* __restrict__ i_idx,
                             int* __restrict__ cnt) {
    int t = blockIdx.x * blockDim.x + threadIdx.x;
    if (t >= NEDGE) return;
    atomicAdd(cnt + __ldg(u_idx + t), 1);
    atomicAdd(cnt + NUSER + __ldg(i_idx + t), 1);
}

// One kernel, 2 blocks of 1024: block 0 = users, block 1 = items.
__global__ void __launch_bounds__(1024)
fused_scan(const int* __restrict__ cnt_all,
           int* __restrict__ rp_u, int* __restrict__ rp_i,
           int* __restrict__ cur_u, int* __restrict__ cur_i,
           float* __restrict__ nu_inv, float* __restrict__ nu_is,
           float* __restrict__ ni_inv, float* __restrict__ ni_is) {
    const bool users = (blockIdx.x == 0);
    const int n = users ? NUSER : NITEM;
    const int* __restrict__ cnt = users ? cnt_all : (cnt_all + NUSER);
    int* __restrict__ rp  = users ? rp_u  : rp_i;
    int* __restrict__ cur = users ? cur_u : cur_i;
    float* __restrict__ inv = users ? nu_inv : ni_inv;
    float* __restrict__ isq = users ? nu_is  : ni_is;

    const int per = (n + 1023) / 1024;
    int beg = threadIdx.x * per;
    int end = min(n, beg + per);

    int s = 0;
    for (int e = beg; e < end; ++e) s += __ldg(cnt + e);

    __shared__ int sh[1024];
    sh[threadIdx.x] = s;
    __syncthreads();
    for (int off = 1; off < 1024; off <<= 1) {
        int t = (threadIdx.x >= off) ? sh[threadIdx.x - off] : 0;
        __syncthreads();
        sh[threadIdx.x] += t;
        __syncthreads();
    }
    int run = sh[threadIdx.x] - s;   // exclusive prefix

    for (int e = beg; e < end; ++e) {
        int c = __ldg(cnt + e);
        rp[e]  = run;
        cur[e] = run;
        float d = c ? (float)c : 1.0f;
        inv[e] = 1.0f / d;
        isq[e] = rsqrtf(d);
        run += c;
    }
    if (threadIdx.x == 0) rp[n] = NEDGE;
}

__global__ void fill_csr(const int* __restrict__ u_idx, const int* __restrict__ i_idx,
                         int* __restrict__ cur_u, int* __restrict__ cur_i,
                         int* __restrict__ cols_u, int* __restrict__ cols_i) {
    int e = blockIdx.x * blockDim.x + threadIdx.x;
    if (e >= NEDGE) return;
    int u = __ldg(u_idx + e);
    int i = __ldg(i_idx + e);
    cols_u[atomicAdd(cur_u + u, 1)] = i;
    cols_i[atomicAdd(cur_i + i, 1)] = u;
}

// ---------------- prescale: P = d^-1/2 * emb  (fp32 -> fp16) ----------------
__global__ void prescale(const float4* __restrict__ ue, const float4* __restrict__ ie,
                         const float* __restrict__ nu_is, const float* __restrict__ ni_is,
                         uint2* __restrict__ pu, uint2* __restrict__ pi) {
    int t = blockIdx.x * blockDim.x + threadIdx.x;
    if (t >= (NUSER + NITEM) * 16) return;
    if (t < NUSER * 16) {
        float s = __ldg(nu_is + (t >> 4));
        float4 v = __ldg(ue + t);
        v.x *= s; v.y *= s; v.z *= s; v.w *= s;
        pu[t] = pack4h(v);
    } else {
        int tt = t - NUSER * 16;
        float s = __ldg(ni_is + (tt >> 4));
        float4 v = __ldg(ie + tt);
        v.x *= s; v.y *= s; v.z *= s; v.w *= s;
        pi[tt] = pack4h(v);
    }
}

// ---------------- phase A: ai = d_i^-1 * RT(pu);  au = d_u^-1 * R(pi) ----------------
__global__ void __launch_bounds__(256)
phaseA(const uint2* __restrict__ pu, const uint2* __restrict__ pi,
       const int* __restrict__ rp_i, const int* __restrict__ cols_i,
       const int* __restrict__ rp_u, const int* __restrict__ cols_u,
       const float* __restrict__ ni_inv, const float* __restrict__ nu_inv,
       uint2* __restrict__ ai, uint2* __restrict__ au) {
    int t = blockIdx.x * blockDim.x + threadIdx.x;
    int r = t >> 4;
    if (r >= NITEM + NUSER) return;
    int c = t & 15;
    unsigned hmask = 0xFFFFu << (threadIdx.x & 16);
    if (r < NITEM) {
        float4 acc = gather_row(pu, cols_i, __ldg(rp_i + r), __ldg(rp_i + r + 1), c, hmask);
        float s = __ldg(ni_inv + r);
        acc.x *= s; acc.y *= s; acc.z *= s; acc.w *= s;
        ai[r * 16 + c] = pack4h(acc);
    } else {
        int u = r - NITEM;
        float4 acc = gather_row(pi, cols_u, __ldg(rp_u + u), __ldg(rp_u + u + 1), c, hmask);
        float s = __ldg(nu_inv + u);
        acc.x *= s; acc.y *= s; acc.z *= s; acc.w *= s;
        au[u * 16 + c] = pack4h(acc);
    }
}

// ---------------- phase B (layers 0..n-2): contribution + next operand ----------------
__global__ void __launch_bounds__(256)
phaseB_mid(const uint2* __restrict__ ai, const uint2* __restrict__ au,
           const int* __restrict__ rp_u, const int* __restrict__ cols_u,
           const int* __restrict__ rp_i, const int* __restrict__ cols_i,
           const float* __restrict__ nu_is, const float* __restrict__ nu_inv,
           const float* __restrict__ ni_is, const float* __restrict__ ni_inv,
           uint2* __restrict__ hc_u, uint2* __restrict__ hc_i,
           uint2* __restrict__ pu, uint2* __restrict__ pi) {
    int t = blockIdx.x * blockDim.x + threadIdx.x;
    int r = t >> 4;
    if (r >= NITEM + NUSER) return;
    int c = t & 15;
    unsigned hmask = 0xFFFFu << (threadIdx.x & 16);
    if (r < NUSER) {
        int idx = r * 16 + c;
        float4 S = gather_row(ai, cols_u, __ldg(rp_u + r), __ldg(rp_u + r + 1), c, hmask);
        float sis = __ldg(nu_is + r);
        float si  = __ldg(nu_inv + r);
        float4 h; h.x = sis * S.x; h.y = sis * S.y; h.z = sis * S.z; h.w = sis * S.w;
        float4 p; p.x = si  * S.x; p.y = si  * S.y; p.z = si  * S.z; p.w = si  * S.w;
        hc_u[idx] = pack4h(h);
        pu[idx]   = pack4h(p);
    } else {
        int i = r - NUSER;
        int idx = i * 16 + c;
        float4 S = gather_row(au, cols_i, __ldg(rp_i + i), __ldg(rp_i + i + 1), c, hmask);
        float sis = __ldg(ni_is + i);
        float si  = __ldg(ni_inv + i);
        float4 h; h.x = sis * S.x; h.y = sis * S.y; h.z = sis * S.z; h.w = sis * S.w;
        float4 p; p.x = si  * S.x; p.y = si  * S.y; p.z = si  * S.z; p.w = si  * S.w;
        hc_i[idx] = pack4h(h);
        pi[idx]   = pack4h(p);
    }
}

// ---------------- phase B (last layer): out = 0.25*(emb + c0 + c1 + d^-1/2 * S) ----------------
__global__ void __launch_bounds__(256)
phaseB_last(const uint2* __restrict__ ai, const uint2* __restrict__ au,
            const int* __restrict__ rp_u, const int* __restrict__ cols_u,
            const int* __restrict__ rp_i, const int* __restrict__ cols_i,
            const float* __restrict__ nu_is, const float* __restrict__ ni_is,
            const float4* __restrict__ emb_u, const float4* __restrict__ emb_i,
            const uint2* __restrict__ hcu0, const uint2* __restrict__ hcu1,
            const uint2* __restrict__ hci0, const uint2* __restrict__ hci1,
            float4* __restrict__ sum_u, float4* __restrict__ sum_i) {
    int t = blockIdx.x * blockDim.x + threadIdx.x;
    int r = t >> 4;
    if (r >= NITEM + NUSER) return;
    int c = t & 15;
    unsigned hmask = 0xFFFFu << (threadIdx.x & 16);
    const float k = 1.0f / (NLAYERS + 1);
    if (r < NUSER) {
        int idx = r * 16 + c;
        float4 S = gather_row(ai, cols_u, __ldg(rp_u + r), __ldg(rp_u + r + 1), c, hmask);
        float sis = __ldg(nu_is + r);
        float4 e  = __ldg(emb_u + idx);
        float4 c0 = unpack4h(__ldg(hcu0 + idx));
        float4 c1 = unpack4h(__ldg(hcu1 + idx));
        float4 o;
        o.x = k * (e.x + c0.x + c1.x + sis * S.x);
        o.y = k * (e.y + c0.y + c1.y + sis * S.y);
        o.z = k * (e.z + c0.z + c1.z + sis * S.z);
        o.w = k * (e.w + c0.w + c1.w + sis * S.w);
        sum_u[idx] = o;
    } else {
        int i = r - NUSER;
        int idx = i * 16 + c;
        float4 S = gather_row(au, cols_i, __ldg(rp_i + i), __ldg(rp_i + i + 1), c, hmask);
        float sis = __ldg(ni_is + i);
        float4 e  = __ldg(emb_i + idx);
        float4 c0 = unpack4h(__ldg(hci0 + idx));
        float4 c1 = unpack4h(__ldg(hci1 + idx));
        float4 o;
        o.x = k * (e.x + c0.x + c1.x + sis * S.x);
        o.y = k * (e.y + c0.y + c1.y + sis * S.y);
        o.z = k * (e.z + c0.z + c1.z + sis * S.z);
        o.w = k * (e.w + c0.w + c1.w + sis * S.w);
        sum_i[idx] = o;
    }
}

// ---------------- launch ----------------
extern "C" void kernel_launch(void* const* d_in, const int* in_sizes, int n_in,
                              void* d_out, int out_size) {
    const float* user_emb = (const float*)d_in[0];
    const float* item_emb = (const float*)d_in[1];
    const int*   u_idx    = (const int*)d_in[2];
    const int*   i_idx    = (const int*)d_in[3];
    float* out = (float*)d_out;
    float* sum_u = out;
    float* sum_i = out + NUSER * DIM;

    __half *p_pu, *p_pi, *p_au, *p_ai, *p_hcu0, *p_hcu1, *p_hci0, *p_hci1;
    float *p_nu_inv, *p_nu_is, *p_ni_inv, *p_ni_is;
    int *p_cnt, *p_rp_u, *p_rp_i, *p_cur_u, *p_cur_i, *p_cols_u, *p_cols_i;
    cudaGetSymbolAddress((void**)&p_pu, g_pu);
    cudaGetSymbolAddress((void**)&p_pi, g_pi);
    cudaGetSymbolAddress((void**)&p_au, g_au);
    cudaGetSymbolAddress((void**)&p_ai, g_ai);
    cudaGetSymbolAddress((void**)&p_hcu0, g_hcu0);
    cudaGetSymbolAddress((void**)&p_hcu1, g_hcu1);
    cudaGetSymbolAddress((void**)&p_hci0, g_hci0);
    cudaGetSymbolAddress((void**)&p_hci1, g_hci1);
    cudaGetSymbolAddress((void**)&p_nu_inv, g_nu_inv);
    cudaGetSymbolAddress((void**)&p_nu_is,  g_nu_is);
    cudaGetSymbolAddress((void**)&p_ni_inv, g_ni_inv);
    cudaGetSymbolAddress((void**)&p_ni_is,  g_ni_is);
    cudaGetSymbolAddress((void**)&p_cnt,    g_cnt);
    cudaGetSymbolAddress((void**)&p_rp_u,   g_rowptr_u);
    cudaGetSymbolAddress((void**)&p_rp_i,   g_rowptr_i);
    cudaGetSymbolAddress((void**)&p_cur_u,  g_cur_u);
    cudaGetSymbolAddress((void**)&p_cur_i,  g_cur_i);
    cudaGetSymbolAddress((void**)&p_cols_u, g_cols_u);
    cudaGetSymbolAddress((void**)&p_cols_i, g_cols_i);

    const int TB = 256;
    const int EDGE_BLKS = (NEDGE + TB - 1) / TB;
    const int ALL_BLKS  = ((NUSER + NITEM) * 16 + TB - 1) / TB;

    // ---- CSR build + norms (5-node prologue) ----
    cudaMemsetAsync(p_cnt, 0, (NUSER + NITEM) * sizeof(int), 0);
    hist_degrees<<<EDGE_BLKS, TB>>>(u_idx, i_idx, p_cnt);
    fused_scan<<<2, 1024>>>(p_cnt, p_rp_u, p_rp_i, p_cur_u, p_cur_i,
                            p_nu_inv, p_nu_is, p_ni_inv, p_ni_is);
    fill_csr<<<EDGE_BLKS, TB>>>(u_idx, i_idx, p_cur_u, p_cur_i, p_cols_u, p_cols_i);

    // ---- initial pre-scaled operands ----
    prescale<<<ALL_BLKS, TB>>>((const float4*)user_emb, (const float4*)item_emb,
                               p_nu_is, p_ni_is, (uint2*)p_pu, (uint2*)p_pi);

    // ---- layers ----
    uint2* HCU[2] = { (uint2*)p_hcu0, (uint2*)p_hcu1 };
    uint2* HCI[2] = { (uint2*)p_hci0, (uint2*)p_hci1 };
    for (int layer = 0; layer < NLAYERS; ++layer) {
        phaseA<<<ALL_BLKS, TB>>>((const uint2*)p_pu, (const uint2*)p_pi,
                                 p_rp_i, p_cols_i, p_rp_u, p_cols_u,
                                 p_ni_inv, p_nu_inv, (uint2*)p_ai, (uint2*)p_au);
        if (layer < NLAYERS - 1) {
            phaseB_mid<<<ALL_BLKS, TB>>>((const uint2*)p_ai, (const uint2*)p_au,
                                         p_rp_u, p_cols_u, p_rp_i, p_cols_i,
                                         p_nu_is, p_nu_inv, p_ni_is, p_ni_inv,
                                         HCU[layer], HCI[layer],
                                         (uint2*)p_pu, (uint2*)p_pi);
        } else {
            phaseB_last<<<ALL_BLKS, TB>>>((const uint2*)p_ai, (const uint2*)p_au,
                                          p_rp_u, p_cols_u, p_rp_i, p_cols_i,
                                          p_nu_is, p_ni_is,
                                          (const float4*)user_emb, (const float4*)item_emb,
                                          (const uint2*)p_hcu0, (const uint2*)p_hcu1,
                                          (const uint2*)p_hci0, (const uint2*)p_hci1,
                                          (float4*)sum_u, (float4*)sum_i);
        }
    }
}

// round 13
// speedup vs baseline: 1.5893x; 1.0062x over previous
#include <cuda_runtime.h>
#include <cuda_fp16.h>

#define NUSER 100000
#define NITEM 50000
#define NEDGE 2000000
#define DIM   64
#define NLAYERS 3

// ---------------- scratch (device globals) ----------------
__device__ __half g_pu[NUSER * DIM];    // pre-scaled user operand
__device__ __half g_pi[NITEM * DIM];    // pre-scaled item operand
__device__ __half g_au[NUSER * DIM];    // phase-A out, user rows (d_u^-1 * R(pi))
__device__ __half g_ai[NITEM * DIM];    // phase-A out, item rows (d_i^-1 * RT(pu))
__device__ __half g_hcu0[NUSER * DIM];  // layer-0 contribution d_u^-1/2 * S_0
__device__ __half g_hcu1[NUSER * DIM];  // layer-1 contribution
__device__ __half g_hci0[NITEM * DIM];
__device__ __half g_hci1[NITEM * DIM];
__device__ int    g_cnt[NUSER + NITEM];
__device__ int    g_rowptr_u[NUSER + 1];
__device__ int    g_rowptr_i[NITEM + 1];
__device__ int    g_cur_u[NUSER];
__device__ int    g_cur_i[NITEM];
__device__ int    g_cols_u[NEDGE];
__device__ int    g_cols_i[NEDGE];
__device__ float  g_nu_inv[NUSER];
__device__ float  g_nu_is [NUSER];
__device__ float  g_ni_inv[NITEM];
__device__ float  g_ni_is [NITEM];

// ---------------- helpers ----------------
__device__ __forceinline__ uint2 pack4h(float4 v) {
    __half2 a = __floats2half2_rn(v.x, v.y);
    __half2 b = __floats2half2_rn(v.z, v.w);
    uint2 r;
    r.x = *reinterpret_cast<unsigned*>(&a);
    r.y = *reinterpret_cast<unsigned*>(&b);
    return r;
}

__device__ __forceinline__ float4 unpack4h(uint2 v) {
    __half2 h0 = *reinterpret_cast<__half2*>(&v.x);
    __half2 h1 = *reinterpret_cast<__half2*>(&v.y);
    float2 f0 = __half22float2(h0);
    float2 f1 = __half22float2(h1);
    return make_float4(f0.x, f0.y, f1.x, f1.y);
}

// gather-add over one CSR row: 16 lanes per row, 8B (4 halves) per lane.
// fp32 accumulation; moderate unroll (MLP_p1 ~ 4 avoids cross-CTA L1tex spread).
// Plain __ldg (L1-allocating): source rows have deg~20-40x temporal reuse;
// L1::no_allocate measured a ~25% clock-normalized regression (round 11).
__device__ __forceinline__ float4 gather_row(const uint2* __restrict__ src,
                                             const int*   __restrict__ cols,
                                             int beg, int end, int c, unsigned hmask) {
    float4 acc = make_float4(0.f, 0.f, 0.f, 0.f);
    for (int base = beg; base < end; base += 16) {
        int myi = base + c;
        int mycol = (myi < end) ? __ldg(cols + myi) : 0;
        int cnt = min(16, end - base);
        #pragma unroll 4
        for (int j = 0; j < cnt; ++j) {
            int col = __shfl_sync(hmask, mycol, j, 16);
            uint2 v = __ldg(src + col * 16 + c);
            float4 f = unpack4h(v);
            acc.x += f.x; acc.y += f.y; acc.z += f.z; acc.w += f.w;
        }
    }
    return acc;
}

// ---------------- CSR build ----------------
__global__ void hist_degrees(const int* __restrict__ u_idx,
                             const int* __restrict__ i_idx,
                             int* __restrict__ cnt) {
    int t = blockIdx.x * blockDim.x + threadIdx.x;
    if (t >= NEDGE) return;
    atomicAdd(cnt + __ldg(u_idx + t), 1);
    atomicAdd(cnt + NUSER + __ldg(i_idx + t), 1);
}

// One kernel, 2 blocks of 1024: block 0 = users, block 1 = items.
__global__ void __launch_bounds__(1024)
fused_scan(const int* __restrict__ cnt_all,
           int* __restrict__ rp_u, int* __restrict__ rp_i,
           int* __restrict__ cur_u, int* __restrict__ cur_i,
           float* __restrict__ nu_inv, float* __restrict__ nu_is,
           float* __restrict__ ni_inv, float* __restrict__ ni_is) {
    const bool users = (blockIdx.x == 0);
    const int n = users ? NUSER : NITEM;
    const int* __restrict__ cnt = users ? cnt_all : (cnt_all + NUSER);
    int* __restrict__ rp  = users ? rp_u  : rp_i;
    int* __restrict__ cur = users ? cur_u : cur_i;
    float* __restrict__ inv = users ? nu_inv : ni_inv;
    float* __restrict__ isq = users ? nu_is  : ni_is;

    const int per = (n + 1023) / 1024;
    int beg = threadIdx.x * per;
    int end = min(n, beg + per);

    int s = 0;
    for (int e = beg; e < end; ++e) s += __ldg(cnt + e);

    __shared__ int sh[1024];
    sh[threadIdx.x] = s;
    __syncthreads();
    for (int off = 1; off < 1024; off <<= 1) {
        int t = (threadIdx.x >= off) ? sh[threadIdx.x - off] : 0;
        __syncthreads();
        sh[threadIdx.x] += t;
        __syncthreads();
    }
    int run = sh[threadIdx.x] - s;   // exclusive prefix

    for (int e = beg; e < end; ++e) {
        int c = __ldg(cnt + e);
        rp[e]  = run;
        cur[e] = run;
        float d = c ? (float)c : 1.0f;
        inv[e] = 1.0f / d;
        isq[e] = rsqrtf(d);
        run += c;
    }
    if (threadIdx.x == 0) rp[n] = NEDGE;
}

// ---------------- fill_csr + prescale fused (independent work, one launch) ----------------
// Blocks [0, EDGE_BLKS): counting-sort fill of both CSR column arrays.
// Blocks [EDGE_BLKS, EDGE_BLKS+ROW_BLKS): P = d^-1/2 * emb  (fp32 -> fp16).
__global__ void __launch_bounds__(256)
fill_and_prescale(const int* __restrict__ u_idx, const int* __restrict__ i_idx,
                  int* __restrict__ cur_u, int* __restrict__ cur_i,
                  int* __restrict__ cols_u, int* __restrict__ cols_i,
                  const float4* __restrict__ ue, const float4* __restrict__ ie,
                  const float* __restrict__ nu_is, const float* __restrict__ ni_is,
                  uint2* __restrict__ pu, uint2* __restrict__ pi,
                  int edge_blks) {
    if (blockIdx.x < (unsigned)edge_blks) {
        int e = blockIdx.x * blockDim.x + threadIdx.x;
        if (e >= NEDGE) return;
        int u = __ldg(u_idx + e);
        int i = __ldg(i_idx + e);
        cols_u[atomicAdd(cur_u + u, 1)] = i;
        cols_i[atomicAdd(cur_i + i, 1)] = u;
    } else {
        int t = (blockIdx.x - edge_blks) * blockDim.x + threadIdx.x;
        if (t >= (NUSER + NITEM) * 16) return;
        if (t < NUSER * 16) {
            float s = __ldg(nu_is + (t >> 4));
            float4 v = __ldg(ue + t);
            v.x *= s; v.y *= s; v.z *= s; v.w *= s;
            pu[t] = pack4h(v);
        } else {
            int tt = t - NUSER * 16;
            float s = __ldg(ni_is + (tt >> 4));
            float4 v = __ldg(ie + tt);
            v.x *= s; v.y *= s; v.z *= s; v.w *= s;
            pi[tt] = pack4h(v);
        }
    }
}

// ---------------- phase A: ai = d_i^-1 * RT(pu);  au = d_u^-1 * R(pi) ----------------
__global__ void __launch_bounds__(256)
phaseA(const uint2* __restrict__ pu, const uint2* __restrict__ pi,
       const int* __restrict__ rp_i, const int* __restrict__ cols_i,
       const int* __restrict__ rp_u, const int* __restrict__ cols_u,
       const float* __restrict__ ni_inv, const float* __restrict__ nu_inv,
       uint2* __restrict__ ai, uint2* __restrict__ au) {
    int t = blockIdx.x * blockDim.x + threadIdx.x;
    int r = t >> 4;
    if (r >= NITEM + NUSER) return;
    int c = t & 15;
    unsigned hmask = 0xFFFFu << (threadIdx.x & 16);
    if (r < NITEM) {
        float4 acc = gather_row(pu, cols_i, __ldg(rp_i + r), __ldg(rp_i + r + 1), c, hmask);
        float s = __ldg(ni_inv + r);
        acc.x *= s; acc.y *= s; acc.z *= s; acc.w *= s;
        ai[r * 16 + c] = pack4h(acc);
    } else {
        int u = r - NITEM;
        float4 acc = gather_row(pi, cols_u, __ldg(rp_u + u), __ldg(rp_u + u + 1), c, hmask);
        float s = __ldg(nu_inv + u);
        acc.x *= s; acc.y *= s; acc.z *= s; acc.w *= s;
        au[u * 16 + c] = pack4h(acc);
    }
}

// ---------------- phase B (layers 0..n-2): contribution + next operand ----------------
__global__ void __launch_bounds__(256)
phaseB_mid(const uint2* __restrict__ ai, const uint2* __restrict__ au,
           const int* __restrict__ rp_u, const int* __restrict__ cols_u,
           const int* __restrict__ rp_i, const int* __restrict__ cols_i,
           const float* __restrict__ nu_is, const float* __restrict__ nu_inv,
           const float* __restrict__ ni_is, const float* __restrict__ ni_inv,
           uint2* __restrict__ hc_u, uint2* __restrict__ hc_i,
           uint2* __restrict__ pu, uint2* __restrict__ pi) {
    int t = blockIdx.x * blockDim.x + threadIdx.x;
    int r = t >> 4;
    if (r >= NITEM + NUSER) return;
    int c = t & 15;
    unsigned hmask = 0xFFFFu << (threadIdx.x & 16);
    if (r < NUSER) {
        int idx = r * 16 + c;
        float4 S = gather_row(ai, cols_u, __ldg(rp_u + r), __ldg(rp_u + r + 1), c, hmask);
        float sis = __ldg(nu_is + r);
        float si  = __ldg(nu_inv + r);
        float4 h; h.x = sis * S.x; h.y = sis * S.y; h.z = sis * S.z; h.w = sis * S.w;
        float4 p; p.x = si  * S.x; p.y = si  * S.y; p.z = si  * S.z; p.w = si  * S.w;
        hc_u[idx] = pack4h(h);
        pu[idx]   = pack4h(p);
    } else {
        int i = r - NUSER;
        int idx = i * 16 + c;
        float4 S = gather_row(au, cols_i, __ldg(rp_i + i), __ldg(rp_i + i + 1), c, hmask);
        float sis = __ldg(ni_is + i);
        float si  = __ldg(ni_inv + i);
        float4 h; h.x = sis * S.x; h.y = sis * S.y; h.z = sis * S.z; h.w = sis * S.w;
        float4 p; p.x = si  * S.x; p.y = si  * S.y; p.z = si  * S.z; p.w = si  * S.w;
        hc_i[idx] = pack4h(h);
        pi[idx]   = pack4h(p);
    }
}

// ---------------- phase B (last layer): out = 0.25*(emb + c0 + c1 + d^-1/2 * S) ----------------
__global__ void __launch_bounds__(256)
phaseB_last(const uint2* __restrict__ ai, const uint2* __restrict__ au,
            const int* __restrict__ rp_u, const int* __restrict__ cols_u,
            const int* __restrict__ rp_i, const int* __restrict__ cols_i,
            const float* __restrict__ nu_is, const float* __restrict__ ni_is,
            const float4* __restrict__ emb_u, const float4* __restrict__ emb_i,
            const uint2* __restrict__ hcu0, const uint2* __restrict__ hcu1,
            const uint2* __restrict__ hci0, const uint2* __restrict__ hci1,
            float4* __restrict__ sum_u, float4* __restrict__ sum_i) {
    int t = blockIdx.x * blockDim.x + threadIdx.x;
    int r = t >> 4;
    if (r >= NITEM + NUSER) return;
    int c = t & 15;
    unsigned hmask = 0xFFFFu << (threadIdx.x & 16);
    const float k = 1.0f / (NLAYERS + 1);
    if (r < NUSER) {
        int idx = r * 16 + c;
        float4 S = gather_row(ai, cols_u, __ldg(rp_u + r), __ldg(rp_u + r + 1), c, hmask);
        float sis = __ldg(nu_is + r);
        float4 e  = __ldg(emb_u + idx);
        float4 c0 = unpack4h(__ldg(hcu0 + idx));
        float4 c1 = unpack4h(__ldg(hcu1 + idx));
        float4 o;
        o.x = k * (e.x + c0.x + c1.x + sis * S.x);
        o.y = k * (e.y + c0.y + c1.y + sis * S.y);
        o.z = k * (e.z + c0.z + c1.z + sis * S.z);
        o.w = k * (e.w + c0.w + c1.w + sis * S.w);
        sum_u[idx] = o;
    } else {
        int i = r - NUSER;
        int idx = i * 16 + c;
        float4 S = gather_row(au, cols_i, __ldg(rp_i + i), __ldg(rp_i + i + 1), c, hmask);
        float sis = __ldg(ni_is + i);
        float4 e  = __ldg(emb_i + idx);
        float4 c0 = unpack4h(__ldg(hci0 + idx));
        float4 c1 = unpack4h(__ldg(hci1 + idx));
        float4 o;
        o.x = k * (e.x + c0.x + c1.x + sis * S.x);
        o.y = k * (e.y + c0.y + c1.y + sis * S.y);
        o.z = k * (e.z + c0.z + c1.z + sis * S.z);
        o.w = k * (e.w + c0.w + c1.w + sis * S.w);
        sum_i[idx] = o;
    }
}

// ---------------- launch ----------------
extern "C" void kernel_launch(void* const* d_in, const int* in_sizes, int n_in,
                              void* d_out, int out_size) {
    const float* user_emb = (const float*)d_in[0];
    const float* item_emb = (const float*)d_in[1];
    const int*   u_idx    = (const int*)d_in[2];
    const int*   i_idx    = (const int*)d_in[3];
    float* out = (float*)d_out;
    float* sum_u = out;
    float* sum_i = out + NUSER * DIM;

    __half *p_pu, *p_pi, *p_au, *p_ai, *p_hcu0, *p_hcu1, *p_hci0, *p_hci1;
    float *p_nu_inv, *p_nu_is, *p_ni_inv, *p_ni_is;
    int *p_cnt, *p_rp_u, *p_rp_i, *p_cur_u, *p_cur_i, *p_cols_u, *p_cols_i;
    cudaGetSymbolAddress((void**)&p_pu, g_pu);
    cudaGetSymbolAddress((void**)&p_pi, g_pi);
    cudaGetSymbolAddress((void**)&p_au, g_au);
    cudaGetSymbolAddress((void**)&p_ai, g_ai);
    cudaGetSymbolAddress((void**)&p_hcu0, g_hcu0);
    cudaGetSymbolAddress((void**)&p_hcu1, g_hcu1);
    cudaGetSymbolAddress((void**)&p_hci0, g_hci0);
    cudaGetSymbolAddress((void**)&p_hci1, g_hci1);
    cudaGetSymbolAddress((void**)&p_nu_inv, g_nu_inv);
    cudaGetSymbolAddress((void**)&p_nu_is,  g_nu_is);
    cudaGetSymbolAddress((void**)&p_ni_inv, g_ni_inv);
    cudaGetSymbolAddress((void**)&p_ni_is,  g_ni_is);
    cudaGetSymbolAddress((void**)&p_cnt,    g_cnt);
    cudaGetSymbolAddress((void**)&p_rp_u,   g_rowptr_u);
    cudaGetSymbolAddress((void**)&p_rp_i,   g_rowptr_i);
    cudaGetSymbolAddress((void**)&p_cur_u,  g_cur_u);
    cudaGetSymbolAddress((void**)&p_cur_i,  g_cur_i);
    cudaGetSymbolAddress((void**)&p_cols_u, g_cols_u);
    cudaGetSymbolAddress((void**)&p_cols_i, g_cols_i);

    const int TB = 256;
    const int EDGE_BLKS = (NEDGE + TB - 1) / TB;
    const int ALL_BLKS  = ((NUSER + NITEM) * 16 + TB - 1) / TB;

    // ---- CSR build + norms + operand init (4-node prologue) ----
    cudaMemsetAsync(p_cnt, 0, (NUSER + NITEM) * sizeof(int), 0);
    hist_degrees<<<EDGE_BLKS, TB>>>(u_idx, i_idx, p_cnt);
    fused_scan<<<2, 1024>>>(p_cnt, p_rp_u, p_rp_i, p_cur_u, p_cur_i,
                            p_nu_inv, p_nu_is, p_ni_inv, p_ni_is);
    fill_and_prescale<<<EDGE_BLKS + ALL_BLKS, TB>>>(
        u_idx, i_idx, p_cur_u, p_cur_i, p_cols_u, p_cols_i,
        (const float4*)user_emb, (const float4*)item_emb,
        p_nu_is, p_ni_is, (uint2*)p_pu, (uint2*)p_pi, EDGE_BLKS);

    // ---- layers ----
    uint2* HCU[2] = { (uint2*)p_hcu0, (uint2*)p_hcu1 };
    uint2* HCI[2] = { (uint2*)p_hci0, (uint2*)p_hci1 };
    for (int layer = 0; layer < NLAYERS; ++layer) {
        phaseA<<<ALL_BLKS, TB>>>((const uint2*)p_pu, (const uint2*)p_pi,
                                 p_rp_i, p_cols_i, p_rp_u, p_cols_u,
                                 p_ni_inv, p_nu_inv, (uint2*)p_ai, (uint2*)p_au);
        if (layer < NLAYERS - 1) {
            phaseB_mid<<<ALL_BLKS, TB>>>((const uint2*)p_ai, (const uint2*)p_au,
                                         p_rp_u, p_cols_u, p_rp_i, p_cols_i,
                                         p_nu_is, p_nu_inv, p_ni_is, p_ni_inv,
                                         HCU[layer], HCI[layer],
                                         (uint2*)p_pu, (uint2*)p_pi);
        } else {
            phaseB_last<<<ALL_BLKS, TB>>>((const uint2*)p_ai, (const uint2*)p_au,
                                          p_rp_u, p_cols_u, p_rp_i, p_cols_i,
                                          p_nu_is, p_ni_is,
                                          (const float4*)user_emb, (const float4*)item_emb,
                                          (const uint2*)p_hcu0, (const uint2*)p_hcu1,
                                          (const uint2*)p_hci0, (const uint2*)p_hci1,
                                          (float4*)sum_u, (float4*)sum_i);
        }
    }
}

// round 14
// speedup vs baseline: 1.6330x; 1.0275x over previous
#include <cuda_runtime.h>
#include <cuda_fp16.h>

#define NUSER 100000
#define NITEM 50000
#define NEDGE 2000000
#define DIM   64
#define NLAYERS 3

// ---------------- scratch (device globals) ----------------
__device__ __half g_pu[NUSER * DIM];    // pre-scaled user operand
__device__ __half g_pi[NITEM * DIM];    // pre-scaled item operand
__device__ __half g_au[NUSER * DIM];    // phase-A out, user rows (d_u^-1 * R(pi))
__device__ __half g_ai[NITEM * DIM];    // phase-A out, item rows (d_i^-1 * RT(pu))
__device__ __half g_hcu0[NUSER * DIM];  // layer-0 contribution d_u^-1/2 * S_0
__device__ __half g_hcu1[NUSER * DIM];  // layer-1 contribution
__device__ __half g_hci0[NITEM * DIM];
__device__ __half g_hci1[NITEM * DIM];
__device__ int    g_cnt[NUSER + NITEM];
__device__ int    g_rowptr_u[NUSER + 1];
__device__ int    g_rowptr_i[NITEM + 1];
__device__ int    g_cur_u[NUSER];
__device__ int    g_cur_i[NITEM];
__device__ int    g_cols_u[NEDGE];
__device__ int    g_cols_i[NEDGE];
__device__ float  g_nu_inv[NUSER];
__device__ float  g_nu_is [NUSER];
__device__ float  g_ni_inv[NITEM];
__device__ float  g_ni_is [NITEM];

// ---------------- helpers ----------------
__device__ __forceinline__ uint2 pack4h(float4 v) {
    __half2 a = __floats2half2_rn(v.x, v.y);
    __half2 b = __floats2half2_rn(v.z, v.w);
    uint2 r;
    r.x = *reinterpret_cast<unsigned*>(&a);
    r.y = *reinterpret_cast<unsigned*>(&b);
    return r;
}

__device__ __forceinline__ float4 unpack4h(uint2 v) {
    __half2 h0 = *reinterpret_cast<__half2*>(&v.x);
    __half2 h1 = *reinterpret_cast<__half2*>(&v.y);
    float2 f0 = __half22float2(h0);
    float2 f1 = __half22float2(h1);
    return make_float4(f0.x, f0.y, f1.x, f1.y);
}

// gather-add over one CSR row: 16 lanes per row, 8B (4 halves) per lane.
// Issue-bound kernel (ncu: issue=74%, L2=37%, L1=41%): accumulate each
// <=16-edge chunk in fp16 via HADD2 (2 instr vs 8 for cvt+fp32 adds),
// spill to fp32 accumulator once per chunk. Chunk-local fp16 error
// ~8e-4/SpMM, ~19x attenuated in final output (measured round 3->8 chain).
// Plain __ldg: L1::no_allocate measured ~25% regression (round 11).
__device__ __forceinline__ float4 gather_row(const uint2* __restrict__ src,
                                             const int*   __restrict__ cols,
                                             int beg, int end, int c, unsigned hmask) {
    float4 acc = make_float4(0.f, 0.f, 0.f, 0.f);
    for (int base = beg; base < end; base += 16) {
        int myi = base + c;
        int mycol = (myi < end) ? __ldg(cols + myi) : 0;
        int cnt = min(16, end - base);
        __half2 h0 = __float2half2_rn(0.f);
        __half2 h1 = __float2half2_rn(0.f);
        #pragma unroll 4
        for (int j = 0; j < cnt; ++j) {
            int col = __shfl_sync(hmask, mycol, j, 16);
            uint2 v = __ldg(src + col * 16 + c);
            h0 = __hadd2(h0, *reinterpret_cast<__half2*>(&v.x));
            h1 = __hadd2(h1, *reinterpret_cast<__half2*>(&v.y));
        }
        float2 f0 = __half22float2(h0);
        float2 f1 = __half22float2(h1);
        acc.x += f0.x; acc.y += f0.y; acc.z += f1.x; acc.w += f1.y;
    }
    return acc;
}

// ---------------- CSR build ----------------
__global__ void hist_degrees(const int* __restrict__ u_idx,
                             const int* __restrict__ i_idx,
                             int* __restrict__ cnt) {
    int t = blockIdx.x * blockDim.x + threadIdx.x;
    if (t >= NEDGE) return;
    atomicAdd(cnt + __ldg(u_idx + t), 1);
    atomicAdd(cnt + NUSER + __ldg(i_idx + t), 1);
}

// One kernel, 2 blocks of 1024: block 0 = users, block 1 = items.
__global__ void __launch_bounds__(1024)
fused_scan(const int* __restrict__ cnt_all,
           int* __restrict__ rp_u, int* __restrict__ rp_i,
           int* __restrict__ cur_u, int* __restrict__ cur_i,
           float* __restrict__ nu_inv, float* __restrict__ nu_is,
           float* __restrict__ ni_inv, float* __restrict__ ni_is) {
    const bool users = (blockIdx.x == 0);
    const int n = users ? NUSER : NITEM;
    const int* __restrict__ cnt = users ? cnt_all : (cnt_all + NUSER);
    int* __restrict__ rp  = users ? rp_u  : rp_i;
    int* __restrict__ cur = users ? cur_u : cur_i;
    float* __restrict__ inv = users ? nu_inv : ni_inv;
    float* __restrict__ isq = users ? nu_is  : ni_is;

    const int per = (n + 1023) / 1024;
    int beg = threadIdx.x * per;
    int end = min(n, beg + per);

    int s = 0;
    for (int e = beg; e < end; ++e) s += __ldg(cnt + e);

    __shared__ int sh[1024];
    sh[threadIdx.x] = s;
    __syncthreads();
    for (int off = 1; off < 1024; off <<= 1) {
        int t = (threadIdx.x >= off) ? sh[threadIdx.x - off] : 0;
        __syncthreads();
        sh[threadIdx.x] += t;
        __syncthreads();
    }
    int run = sh[threadIdx.x] - s;   // exclusive prefix

    for (int e = beg; e < end; ++e) {
        int c = __ldg(cnt + e);
        rp[e]  = run;
        cur[e] = run;
        float d = c ? (float)c : 1.0f;
        inv[e] = 1.0f / d;
        isq[e] = rsqrtf(d);
        run += c;
    }
    if (threadIdx.x == 0) rp[n] = NEDGE;
}

// ---------------- fill_csr + prescale fused (independent work, one launch) ----------------
__global__ void __launch_bounds__(256)
fill_and_prescale(const int* __restrict__ u_idx, const int* __restrict__ i_idx,
                  int* __restrict__ cur_u, int* __restrict__ cur_i,
                  int* __restrict__ cols_u, int* __restrict__ cols_i,
                  const float4* __restrict__ ue, const float4* __restrict__ ie,
                  const float* __restrict__ nu_is, const float* __restrict__ ni_is,
                  uint2* __restrict__ pu, uint2* __restrict__ pi,
                  int edge_blks) {
    if (blockIdx.x < (unsigned)edge_blks) {
        int e = blockIdx.x * blockDim.x + threadIdx.x;
        if (e >= NEDGE) return;
        int u = __ldg(u_idx + e);
        int i = __ldg(i_idx + e);
        cols_u[atomicAdd(cur_u + u, 1)] = i;
        cols_i[atomicAdd(cur_i + i, 1)] = u;
    } else {
        int t = (blockIdx.x - edge_blks) * blockDim.x + threadIdx.x;
        if (t >= (NUSER + NITEM) * 16) return;
        if (t < NUSER * 16) {
            float s = __ldg(nu_is + (t >> 4));
            float4 v = __ldg(ue + t);
            v.x *= s; v.y *= s; v.z *= s; v.w *= s;
            pu[t] = pack4h(v);
        } else {
            int tt = t - NUSER * 16;
            float s = __ldg(ni_is + (tt >> 4));
            float4 v = __ldg(ie + tt);
            v.x *= s; v.y *= s; v.z *= s; v.w *= s;
            pi[tt] = pack4h(v);
        }
    }
}

// ---------------- phase A: ai = d_i^-1 * RT(pu);  au = d_u^-1 * R(pi) ----------------
__global__ void __launch_bounds__(256)
phaseA(const uint2* __restrict__ pu, const uint2* __restrict__ pi,
       const int* __restrict__ rp_i, const int* __restrict__ cols_i,
       const int* __restrict__ rp_u, const int* __restrict__ cols_u,
       const float* __restrict__ ni_inv, const float* __restrict__ nu_inv,
       uint2* __restrict__ ai, uint2* __restrict__ au) {
    int t = blockIdx.x * blockDim.x + threadIdx.x;
    int r = t >> 4;
    if (r >= NITEM + NUSER) return;
    int c = t & 15;
    unsigned hmask = 0xFFFFu << (threadIdx.x & 16);
    if (r < NITEM) {
        float4 acc = gather_row(pu, cols_i, __ldg(rp_i + r), __ldg(rp_i + r + 1), c, hmask);
        float s = __ldg(ni_inv + r);
        acc.x *= s; acc.y *= s; acc.z *= s; acc.w *= s;
        ai[r * 16 + c] = pack4h(acc);
    } else {
        int u = r - NITEM;
        float4 acc = gather_row(pi, cols_u, __ldg(rp_u + u), __ldg(rp_u + u + 1), c, hmask);
        float s = __ldg(nu_inv + u);
        acc.x *= s; acc.y *= s; acc.z *= s; acc.w *= s;
        au[u * 16 + c] = pack4h(acc);
    }
}

// ---------------- phase B (layers 0..n-2): contribution + next operand ----------------
__global__ void __launch_bounds__(256)
phaseB_mid(const uint2* __restrict__ ai, const uint2* __restrict__ au,
           const int* __restrict__ rp_u, const int* __restrict__ cols_u,
           const int* __restrict__ rp_i, const int* __restrict__ cols_i,
           const float* __restrict__ nu_is, const float* __restrict__ nu_inv,
           const float* __restrict__ ni_is, const float* __restrict__ ni_inv,
           uint2* __restrict__ hc_u, uint2* __restrict__ hc_i,
           uint2* __restrict__ pu, uint2* __restrict__ pi) {
    int t = blockIdx.x * blockDim.x + threadIdx.x;
    int r = t >> 4;
    if (r >= NITEM + NUSER) return;
    int c = t & 15;
    unsigned hmask = 0xFFFFu << (threadIdx.x & 16);
    if (r < NUSER) {
        int idx = r * 16 + c;
        float4 S = gather_row(ai, cols_u, __ldg(rp_u + r), __ldg(rp_u + r + 1), c, hmask);
        float sis = __ldg(nu_is + r);
        float si  = __ldg(nu_inv + r);
        float4 h; h.x = sis * S.x; h.y = sis * S.y; h.z = sis * S.z; h.w = sis * S.w;
        float4 p; p.x = si  * S.x; p.y = si  * S.y; p.z = si  * S.z; p.w = si  * S.w;
        hc_u[idx] = pack4h(h);
        pu[idx]   = pack4h(p);
    } else {
        int i = r - NUSER;
        int idx = i * 16 + c;
        float4 S = gather_row(au, cols_i, __ldg(rp_i + i), __ldg(rp_i + i + 1), c, hmask);
        float sis = __ldg(ni_is + i);
        float si  = __ldg(ni_inv + i);
        float4 h; h.x = sis * S.x; h.y = sis * S.y; h.z = sis * S.z; h.w = sis * S.w;
        float4 p; p.x = si  * S.x; p.y = si  * S.y; p.z = si  * S.z; p.w = si  * S.w;
        hc_i[idx] = pack4h(h);
        pi[idx]   = pack4h(p);
    }
}

// ---------------- phase B (last layer): out = 0.25*(emb + c0 + c1 + d^-1/2 * S) ----------------
__global__ void __launch_bounds__(256)
phaseB_last(const uint2* __restrict__ ai, const uint2* __restrict__ au,
            const int* __restrict__ rp_u, const int* __restrict__ cols_u,
            const int* __restrict__ rp_i, const int* __restrict__ cols_i,
            const float* __restrict__ nu_is, const float* __restrict__ ni_is,
            const float4* __restrict__ emb_u, const float4* __restrict__ emb_i,
            const uint2* __restrict__ hcu0, const uint2* __restrict__ hcu1,
            const uint2* __restrict__ hci0, const uint2* __restrict__ hci1,
            float4* __restrict__ sum_u, float4* __restrict__ sum_i) {
    int t = blockIdx.x * blockDim.x + threadIdx.x;
    int r = t >> 4;
    if (r >= NITEM + NUSER) return;
    int c = t & 15;
    unsigned hmask = 0xFFFFu << (threadIdx.x & 16);
    const float k = 1.0f / (NLAYERS + 1);
    if (r < NUSER) {
        int idx = r * 16 + c;
        float4 S = gather_row(ai, cols_u, __ldg(rp_u + r), __ldg(rp_u + r + 1), c, hmask);
        float sis = __ldg(nu_is + r);
        float4 e  = __ldg(emb_u + idx);
        float4 c0 = unpack4h(__ldg(hcu0 + idx));
        float4 c1 = unpack4h(__ldg(hcu1 + idx));
        float4 o;
        o.x = k * (e.x + c0.x + c1.x + sis * S.x);
        o.y = k * (e.y + c0.y + c1.y + sis * S.y);
        o.z = k * (e.z + c0.z + c1.z + sis * S.z);
        o.w = k * (e.w + c0.w + c1.w + sis * S.w);
        sum_u[idx] = o;
    } else {
        int i = r - NUSER;
        int idx = i * 16 + c;
        float4 S = gather_row(au, cols_i, __ldg(rp_i + i), __ldg(rp_i + i + 1), c, hmask);
        float sis = __ldg(ni_is + i);
        float4 e  = __ldg(emb_i + idx);
        float4 c0 = unpack4h(__ldg(hci0 + idx));
        float4 c1 = unpack4h(__ldg(hci1 + idx));
        float4 o;
        o.x = k * (e.x + c0.x + c1.x + sis * S.x);
        o.y = k * (e.y + c0.y + c1.y + sis * S.y);
        o.z = k * (e.z + c0.z + c1.z + sis * S.z);
        o.w = k * (e.w + c0.w + c1.w + sis * S.w);
        sum_i[idx] = o;
    }
}

// ---------------- launch ----------------
extern "C" void kernel_launch(void* const* d_in, const int* in_sizes, int n_in,
                              void* d_out, int out_size) {
    const float* user_emb = (const float*)d_in[0];
    const float* item_emb = (const float*)d_in[1];
    const int*   u_idx    = (const int*)d_in[2];
    const int*   i_idx    = (const int*)d_in[3];
    float* out = (float*)d_out;
    float* sum_u = out;
    float* sum_i = out + NUSER * DIM;

    __half *p_pu, *p_pi, *p_au, *p_ai, *p_hcu0, *p_hcu1, *p_hci0, *p_hci1;
    float *p_nu_inv, *p_nu_is, *p_ni_inv, *p_ni_is;
    int *p_cnt, *p_rp_u, *p_rp_i, *p_cur_u, *p_cur_i, *p_cols_u, *p_cols_i;
    cudaGetSymbolAddress((void**)&p_pu, g_pu);
    cudaGetSymbolAddress((void**)&p_pi, g_pi);
    cudaGetSymbolAddress((void**)&p_au, g_au);
    cudaGetSymbolAddress((void**)&p_ai, g_ai);
    cudaGetSymbolAddress((void**)&p_hcu0, g_hcu0);
    cudaGetSymbolAddress((void**)&p_hcu1, g_hcu1);
    cudaGetSymbolAddress((void**)&p_hci0, g_hci0);
    cudaGetSymbolAddress((void**)&p_hci1, g_hci1);
    cudaGetSymbolAddress((void**)&p_nu_inv, g_nu_inv);
    cudaGetSymbolAddress((void**)&p_nu_is,  g_nu_is);
    cudaGetSymbolAddress((void**)&p_ni_inv, g_ni_inv);
    cudaGetSymbolAddress((void**)&p_ni_is,  g_ni_is);
    cudaGetSymbolAddress((void**)&p_cnt,    g_cnt);
    cudaGetSymbolAddress((void**)&p_rp_u,   g_rowptr_u);
    cudaGetSymbolAddress((void**)&p_rp_i,   g_rowptr_i);
    cudaGetSymbolAddress((void**)&p_cur_u,  g_cur_u);
    cudaGetSymbolAddress((void**)&p_cur_i,  g_cur_i);
    cudaGetSymbolAddress((void**)&p_cols_u, g_cols_u);
    cudaGetSymbolAddress((void**)&p_cols_i, g_cols_i);

    const int TB = 256;
    const int EDGE_BLKS = (NEDGE + TB - 1) / TB;
    const int ALL_BLKS  = ((NUSER + NITEM) * 16 + TB - 1) / TB;

    // ---- CSR build + norms + operand init (4-node prologue) ----
    cudaMemsetAsync(p_cnt, 0, (NUSER + NITEM) * sizeof(int), 0);
    hist_degrees<<<EDGE_BLKS, TB>>>(u_idx, i_idx, p_cnt);
    fused_scan<<<2, 1024>>>(p_cnt, p_rp_u, p_rp_i, p_cur_u, p_cur_i,
                            p_nu_inv, p_nu_is, p_ni_inv, p_ni_is);
    fill_and_prescale<<<EDGE_BLKS + ALL_BLKS, TB>>>(
        u_idx, i_idx, p_cur_u, p_cur_i, p_cols_u, p_cols_i,
        (const float4*)user_emb, (const float4*)item_emb,
        p_nu_is, p_ni_is, (uint2*)p_pu, (uint2*)p_pi, EDGE_BLKS);

    // ---- layers ----
    uint2* HCU[2] = { (uint2*)p_hcu0, (uint2*)p_hcu1 };
    uint2* HCI[2] = { (uint2*)p_hci0, (uint2*)p_hci1 };
    for (int layer = 0; layer < NLAYERS; ++layer) {
        phaseA<<<ALL_BLKS, TB>>>((const uint2*)p_pu, (const uint2*)p_pi,
                                 p_rp_i, p_cols_i, p_rp_u, p_cols_u,
                                 p_ni_inv, p_nu_inv, (uint2*)p_ai, (uint2*)p_au);
        if (layer < NLAYERS - 1) {
            phaseB_mid<<<ALL_BLKS, TB>>>((const uint2*)p_ai, (const uint2*)p_au,
                                         p_rp_u, p_cols_u, p_rp_i, p_cols_i,
                                         p_nu_is, p_nu_inv, p_ni_is, p_ni_inv,
                                         HCU[layer], HCI[layer],
                                         (uint2*)p_pu, (uint2*)p_pi);
        } else {
            phaseB_last<<<ALL_BLKS, TB>>>((const uint2*)p_ai, (const uint2*)p_au,
                                          p_rp_u, p_cols_u, p_rp_i, p_cols_i,
                                          p_nu_is, p_ni_is,
                                          (const float4*)user_emb, (const float4*)item_emb,
                                          (const uint2*)p_hcu0, (const uint2*)p_hcu1,
                                          (const uint2*)p_hci0, (const uint2*)p_hci1,
                                          (float4*)sum_u, (float4*)sum_i);
        }
    }
}

// round 15
// speedup vs baseline: 1.6941x; 1.0374x over previous
#include <cuda_runtime.h>
#include <cuda_fp16.h>

#define NUSER 100000
#define NITEM 50000
#define NEDGE 2000000
#define DIM   64
#define NLAYERS 3

// ---------------- scratch (device globals) ----------------
__device__ __half g_pu[NUSER * DIM];    // pre-scaled user operand
__device__ __half g_pi[NITEM * DIM];    // pre-scaled item operand
__device__ __half g_au[NUSER * DIM];    // phase-A out, user rows (d_u^-1 * R(pi))
__device__ __half g_ai[NITEM * DIM];    // phase-A out, item rows (d_i^-1 * RT(pu))
__device__ __half g_hcu0[NUSER * DIM];  // layer-0 contribution d_u^-1/2 * S_0
__device__ __half g_hcu1[NUSER * DIM];  // layer-1 contribution
__device__ __half g_hci0[NITEM * DIM];
__device__ __half g_hci1[NITEM * DIM];
__device__ int    g_cnt[NUSER + NITEM];
__device__ int    g_rowptr_u[NUSER + 1];
__device__ int    g_rowptr_i[NITEM + 1];
__device__ int    g_cur_u[NUSER];
__device__ int    g_cur_i[NITEM];
__device__ int    g_cols_u[NEDGE];
__device__ int    g_cols_i[NEDGE];
__device__ float  g_nu_inv[NUSER];
__device__ float  g_nu_is [NUSER];
__device__ float  g_ni_inv[NITEM];
__device__ float  g_ni_is [NITEM];

// ---------------- helpers ----------------
__device__ __forceinline__ uint2 pack4h(float4 v) {
    __half2 a = __floats2half2_rn(v.x, v.y);
    __half2 b = __floats2half2_rn(v.z, v.w);
    uint2 r;
    r.x = *reinterpret_cast<unsigned*>(&a);
    r.y = *reinterpret_cast<unsigned*>(&b);
    return r;
}

__device__ __forceinline__ uint4 pack8h(const float* f) {
    __half2 a = __floats2half2_rn(f[0], f[1]);
    __half2 b = __floats2half2_rn(f[2], f[3]);
    __half2 c = __floats2half2_rn(f[4], f[5]);
    __half2 d = __floats2half2_rn(f[6], f[7]);
    uint4 r;
    r.x = *reinterpret_cast<unsigned*>(&a);
    r.y = *reinterpret_cast<unsigned*>(&b);
    r.z = *reinterpret_cast<unsigned*>(&c);
    r.w = *reinterpret_cast<unsigned*>(&d);
    return r;
}

__device__ __forceinline__ void unpack8h(uint4 v, float* f) {
    float2 f0 = __half22float2(*reinterpret_cast<__half2*>(&v.x));
    float2 f1 = __half22float2(*reinterpret_cast<__half2*>(&v.y));
    float2 f2 = __half22float2(*reinterpret_cast<__half2*>(&v.z));
    float2 f3 = __half22float2(*reinterpret_cast<__half2*>(&v.w));
    f[0] = f0.x; f[1] = f0.y; f[2] = f1.x; f[3] = f1.y;
    f[4] = f2.x; f[5] = f2.y; f[6] = f3.x; f[7] = f3.y;
}

// gather-add over one CSR row: 8 lanes per row, 16B (8 halves) per lane.
// Issue-dominated kernel (ncu R13/14): minimize instructions per edge.
// Per edge per lane: SHFL + IMAD + LDG.128 + 4x HADD2. Chunk (<=8 edges)
// accumulates in fp16, spills to fp32 acc per chunk (error ~ same as the
// validated 16-edge fp16 chunks; rel_err 4e-5 band).
// Plain __ldg: L1::no_allocate measured ~25% regression (round 11).
__device__ __forceinline__ void gather_row8(const uint4* __restrict__ src,
                                            const int*   __restrict__ cols,
                                            int beg, int end, int c, unsigned qmask,
                                            float* acc) {
    for (int base = beg; base < end; base += 8) {
        int myi = base + c;
        int mycol = (myi < end) ? __ldg(cols + myi) : 0;
        int cnt = min(8, end - base);
        __half2 h0 = __float2half2_rn(0.f);
        __half2 h1 = h0, h2 = h0, h3 = h0;
        #pragma unroll 4
        for (int j = 0; j < cnt; ++j) {
            int col = __shfl_sync(qmask, mycol, j, 8);
            uint4 v = __ldg(src + col * 8 + c);
            h0 = __hadd2(h0, *reinterpret_cast<__half2*>(&v.x));
            h1 = __hadd2(h1, *reinterpret_cast<__half2*>(&v.y));
            h2 = __hadd2(h2, *reinterpret_cast<__half2*>(&v.z));
            h3 = __hadd2(h3, *reinterpret_cast<__half2*>(&v.w));
        }
        float2 f0 = __half22float2(h0);
        float2 f1 = __half22float2(h1);
        float2 f2 = __half22float2(h2);
        float2 f3 = __half22float2(h3);
        acc[0] += f0.x; acc[1] += f0.y; acc[2] += f1.x; acc[3] += f1.y;
        acc[4] += f2.x; acc[5] += f2.y; acc[6] += f3.x; acc[7] += f3.y;
    }
}

// ---------------- CSR build ----------------
__global__ void hist_degrees(const int* __restrict__ u_idx,
                             const int* __restrict__ i_idx,
                             int* __restrict__ cnt) {
    int t = blockIdx.x * blockDim.x + threadIdx.x;
    if (t >= NEDGE) return;
    atomicAdd(cnt + __ldg(u_idx + t), 1);
    atomicAdd(cnt + NUSER + __ldg(i_idx + t), 1);
}

// One kernel, 2 blocks of 1024: block 0 = users, block 1 = items.
__global__ void __launch_bounds__(1024)
fused_scan(const int* __restrict__ cnt_all,
           int* __restrict__ rp_u, int* __restrict__ rp_i,
           int* __restrict__ cur_u, int* __restrict__ cur_i,
           float* __restrict__ nu_inv, float* __restrict__ nu_is,
           float* __restrict__ ni_inv, float* __restrict__ ni_is) {
    const bool users = (blockIdx.x == 0);
    const int n = users ? NUSER : NITEM;
    const int* __restrict__ cnt = users ? cnt_all : (cnt_all + NUSER);
    int* __restrict__ rp  = users ? rp_u  : rp_i;
    int* __restrict__ cur = users ? cur_u : cur_i;
    float* __restrict__ inv = users ? nu_inv : ni_inv;
    float* __restrict__ isq = users ? nu_is  : ni_is;

    const int per = (n + 1023) / 1024;
    int beg = threadIdx.x * per;
    int end = min(n, beg + per);

    int s = 0;
    for (int e = beg; e < end; ++e) s += __ldg(cnt + e);

    __shared__ int sh[1024];
    sh[threadIdx.x] = s;
    __syncthreads();
    for (int off = 1; off < 1024; off <<= 1) {
        int t = (threadIdx.x >= off) ? sh[threadIdx.x - off] : 0;
        __syncthreads();
        sh[threadIdx.x] += t;
        __syncthreads();
    }
    int run = sh[threadIdx.x] - s;   // exclusive prefix

    for (int e = beg; e < end; ++e) {
        int c = __ldg(cnt + e);
        rp[e]  = run;
        cur[e] = run;
        float d = c ? (float)c : 1.0f;
        inv[e] = 1.0f / d;
        isq[e] = rsqrtf(d);
        run += c;
    }
    if (threadIdx.x == 0) rp[n] = NEDGE;
}

// ---------------- fill_csr + prescale fused (independent work, one launch) ----------------
__global__ void __launch_bounds__(256)
fill_and_prescale(const int* __restrict__ u_idx, const int* __restrict__ i_idx,
                  int* __restrict__ cur_u, int* __restrict__ cur_i,
                  int* __restrict__ cols_u, int* __restrict__ cols_i,
                  const float4* __restrict__ ue, const float4* __restrict__ ie,
                  const float* __restrict__ nu_is, const float* __restrict__ ni_is,
                  uint2* __restrict__ pu, uint2* __restrict__ pi,
                  int edge_blks) {
    if (blockIdx.x < (unsigned)edge_blks) {
        int e = blockIdx.x * blockDim.x + threadIdx.x;
        if (e >= NEDGE) return;
        int u = __ldg(u_idx + e);
        int i = __ldg(i_idx + e);
        cols_u[atomicAdd(cur_u + u, 1)] = i;
        cols_i[atomicAdd(cur_i + i, 1)] = u;
    } else {
        int t = (blockIdx.x - edge_blks) * blockDim.x + threadIdx.x;
        if (t >= (NUSER + NITEM) * 16) return;
        if (t < NUSER * 16) {
            float s = __ldg(nu_is + (t >> 4));
            float4 v = __ldg(ue + t);
            v.x *= s; v.y *= s; v.z *= s; v.w *= s;
            pu[t] = pack4h(v);
        } else {
            int tt = t - NUSER * 16;
            float s = __ldg(ni_is + (tt >> 4));
            float4 v = __ldg(ie + tt);
            v.x *= s; v.y *= s; v.z *= s; v.w *= s;
            pi[tt] = pack4h(v);
        }
    }
}

// ---------------- phase A: ai = d_i^-1 * RT(pu);  au = d_u^-1 * R(pi) ----------------
__global__ void __launch_bounds__(256)
phaseA(const uint4* __restrict__ pu, const uint4* __restrict__ pi,
       const int* __restrict__ rp_i, const int* __restrict__ cols_i,
       const int* __restrict__ rp_u, const int* __restrict__ cols_u,
       const float* __restrict__ ni_inv, const float* __restrict__ nu_inv,
       uint4* __restrict__ ai, uint4* __restrict__ au) {
    int t = blockIdx.x * blockDim.x + threadIdx.x;
    int r = t >> 3;
    if (r >= NITEM + NUSER) return;
    int c = t & 7;
    unsigned qmask = 0xFFu << (threadIdx.x & 24);
    float acc[8] = {0,0,0,0,0,0,0,0};
    if (r < NITEM) {
        gather_row8(pu, cols_i, __ldg(rp_i + r), __ldg(rp_i + r + 1), c, qmask, acc);
        float s = __ldg(ni_inv + r);
        #pragma unroll
        for (int k = 0; k < 8; ++k) acc[k] *= s;
        ai[r * 8 + c] = pack8h(acc);
    } else {
        int u = r - NITEM;
        gather_row8(pi, cols_u, __ldg(rp_u + u), __ldg(rp_u + u + 1), c, qmask, acc);
        float s = __ldg(nu_inv + u);
        #pragma unroll
        for (int k = 0; k < 8; ++k) acc[k] *= s;
        au[u * 8 + c] = pack8h(acc);
    }
}

// ---------------- phase B (layers 0..n-2): contribution + next operand ----------------
__global__ void __launch_bounds__(256)
phaseB_mid(const uint4* __restrict__ ai, const uint4* __restrict__ au,
           const int* __restrict__ rp_u, const int* __restrict__ cols_u,
           const int* __restrict__ rp_i, const int* __restrict__ cols_i,
           const float* __restrict__ nu_is, const float* __restrict__ nu_inv,
           const float* __restrict__ ni_is, const float* __restrict__ ni_inv,
           uint4* __restrict__ hc_u, uint4* __restrict__ hc_i,
           uint4* __restrict__ pu, uint4* __restrict__ pi) {
    int t = blockIdx.x * blockDim.x + threadIdx.x;
    int r = t >> 3;
    if (r >= NITEM + NUSER) return;
    int c = t & 7;
    unsigned qmask = 0xFFu << (threadIdx.x & 24);
    float S[8] = {0,0,0,0,0,0,0,0};
    if (r < NUSER) {
        int idx = r * 8 + c;
        gather_row8(ai, cols_u, __ldg(rp_u + r), __ldg(rp_u + r + 1), c, qmask, S);
        float sis = __ldg(nu_is + r);
        float si  = __ldg(nu_inv + r);
        float h[8], p[8];
        #pragma unroll
        for (int k = 0; k < 8; ++k) { h[k] = sis * S[k]; p[k] = si * S[k]; }
        hc_u[idx] = pack8h(h);
        pu[idx]   = pack8h(p);
    } else {
        int i = r - NUSER;
        int idx = i * 8 + c;
        gather_row8(au, cols_i, __ldg(rp_i + i), __ldg(rp_i + i + 1), c, qmask, S);
        float sis = __ldg(ni_is + i);
        float si  = __ldg(ni_inv + i);
        float h[8], p[8];
        #pragma unroll
        for (int k = 0; k < 8; ++k) { h[k] = sis * S[k]; p[k] = si * S[k]; }
        hc_i[idx] = pack8h(h);
        pi[idx]   = pack8h(p);
    }
}

// ---------------- phase B (last layer): out = 0.25*(emb + c0 + c1 + d^-1/2 * S) ----------------
__global__ void __launch_bounds__(256)
phaseB_last(const uint4* __restrict__ ai, const uint4* __restrict__ au,
            const int* __restrict__ rp_u, const int* __restrict__ cols_u,
            const int* __restrict__ rp_i, const int* __restrict__ cols_i,
            const float* __restrict__ nu_is, const float* __restrict__ ni_is,
            const float4* __restrict__ emb_u, const float4* __restrict__ emb_i,
            const uint4* __restrict__ hcu0, const uint4* __restrict__ hcu1,
            const uint4* __restrict__ hci0, const uint4* __restrict__ hci1,
            float4* __restrict__ sum_u, float4* __restrict__ sum_i) {
    int t = blockIdx.x * blockDim.x + threadIdx.x;
    int r = t >> 3;
    if (r >= NITEM + NUSER) return;
    int c = t & 7;
    unsigned qmask = 0xFFu << (threadIdx.x & 24);
    const float k = 1.0f / (NLAYERS + 1);
    float S[8] = {0,0,0,0,0,0,0,0};
    const float4* emb; float4* sum;
    const uint4 *h0p, *h1p; float sis; int idx;
    if (r < NUSER) {
        gather_row8(ai, cols_u, __ldg(rp_u + r), __ldg(rp_u + r + 1), c, qmask, S);
        sis = __ldg(nu_is + r);
        emb = emb_u; sum = sum_u; h0p = hcu0; h1p = hcu1; idx = r * 8 + c;
    } else {
        int i = r - NUSER;
        gather_row8(au, cols_i, __ldg(rp_i + i), __ldg(rp_i + i + 1), c, qmask, S);
        sis = __ldg(ni_is + i);
        emb = emb_i; sum = sum_i; h0p = hci0; h1p = hci1; idx = i * 8 + c;
    }
    float c0[8], c1[8];
    unpack8h(__ldg(h0p + idx), c0);
    unpack8h(__ldg(h1p + idx), c1);
    float4 e0 = __ldg(emb + idx * 2);
    float4 e1 = __ldg(emb + idx * 2 + 1);
    float4 o0, o1;
    o0.x = k * (e0.x + c0[0] + c1[0] + sis * S[0]);
    o0.y = k * (e0.y + c0[1] + c1[1] + sis * S[1]);
    o0.z = k * (e0.z + c0[2] + c1[2] + sis * S[2]);
    o0.w = k * (e0.w + c0[3] + c1[3] + sis * S[3]);
    o1.x = k * (e1.x + c0[4] + c1[4] + sis * S[4]);
    o1.y = k * (e1.y + c0[5] + c1[5] + sis * S[5]);
    o1.z = k * (e1.z + c0[6] + c1[6] + sis * S[6]);
    o1.w = k * (e1.w + c0[7] + c1[7] + sis * S[7]);
    sum[idx * 2]     = o0;
    sum[idx * 2 + 1] = o1;
}

// ---------------- launch ----------------
extern "C" void kernel_launch(void* const* d_in, const int* in_sizes, int n_in,
                              void* d_out, int out_size) {
    const float* user_emb = (const float*)d_in[0];
    const float* item_emb = (const float*)d_in[1];
    const int*   u_idx    = (const int*)d_in[2];
    const int*   i_idx    = (const int*)d_in[3];
    float* out = (float*)d_out;
    float* sum_u = out;
    float* sum_i = out + NUSER * DIM;

    __half *p_pu, *p_pi, *p_au, *p_ai, *p_hcu0, *p_hcu1, *p_hci0, *p_hci1;
    float *p_nu_inv, *p_nu_is, *p_ni_inv, *p_ni_is;
    int *p_cnt, *p_rp_u, *p_rp_i, *p_cur_u, *p_cur_i, *p_cols_u, *p_cols_i;
    cudaGetSymbolAddress((void**)&p_pu, g_pu);
    cudaGetSymbolAddress((void**)&p_pi, g_pi);
    cudaGetSymbolAddress((void**)&p_au, g_au);
    cudaGetSymbolAddress((void**)&p_ai, g_ai);
    cudaGetSymbolAddress((void**)&p_hcu0, g_hcu0);
    cudaGetSymbolAddress((void**)&p_hcu1, g_hcu1);
    cudaGetSymbolAddress((void**)&p_hci0, g_hci0);
    cudaGetSymbolAddress((void**)&p_hci1, g_hci1);
    cudaGetSymbolAddress((void**)&p_nu_inv, g_nu_inv);
    cudaGetSymbolAddress((void**)&p_nu_is,  g_nu_is);
    cudaGetSymbolAddress((void**)&p_ni_inv, g_ni_inv);
    cudaGetSymbolAddress((void**)&p_ni_is,  g_ni_is);
    cudaGetSymbolAddress((void**)&p_cnt,    g_cnt);
    cudaGetSymbolAddress((void**)&p_rp_u,   g_rowptr_u);
    cudaGetSymbolAddress((void**)&p_rp_i,   g_rowptr_i);
    cudaGetSymbolAddress((void**)&p_cur_u,  g_cur_u);
    cudaGetSymbolAddress((void**)&p_cur_i,  g_cur_i);
    cudaGetSymbolAddress((void**)&p_cols_u, g_cols_u);
    cudaGetSymbolAddress((void**)&p_cols_i, g_cols_i);

    const int TB = 256;
    const int EDGE_BLKS = (NEDGE + TB - 1) / TB;
    const int PRE_BLKS  = ((NUSER + NITEM) * 16 + TB - 1) / TB;
    const int ALL_BLKS  = ((NUSER + NITEM) * 8 + TB - 1) / TB;

    // ---- CSR build + norms + operand init (4-node prologue) ----
    cudaMemsetAsync(p_cnt, 0, (NUSER + NITEM) * sizeof(int), 0);
    hist_degrees<<<EDGE_BLKS, TB>>>(u_idx, i_idx, p_cnt);
    fused_scan<<<2, 1024>>>(p_cnt, p_rp_u, p_rp_i, p_cur_u, p_cur_i,
                            p_nu_inv, p_nu_is, p_ni_inv, p_ni_is);
    fill_and_prescale<<<EDGE_BLKS + PRE_BLKS, TB>>>(
        u_idx, i_idx, p_cur_u, p_cur_i, p_cols_u, p_cols_i,
        (const float4*)user_emb, (const float4*)item_emb,
        p_nu_is, p_ni_is, (uint2*)p_pu, (uint2*)p_pi, EDGE_BLKS);

    // ---- layers ----
    uint4* HCU[2] = { (uint4*)p_hcu0, (uint4*)p_hcu1 };
    uint4* HCI[2] = { (uint4*)p_hci0, (uint4*)p_hci1 };
    for (int layer = 0; layer < NLAYERS; ++layer) {
        phaseA<<<ALL_BLKS, TB>>>((const uint4*)p_pu, (const uint4*)p_pi,
                                 p_rp_i, p_cols_i, p_rp_u, p_cols_u,
                                 p_ni_inv, p_nu_inv, (uint4*)p_ai, (uint4*)p_au);
        if (layer < NLAYERS - 1) {
            phaseB_mid<<<ALL_BLKS, TB>>>((const uint4*)p_ai, (const uint4*)p_au,
                                         p_rp_u, p_cols_u, p_rp_i, p_cols_i,
                                         p_nu_is, p_nu_inv, p_ni_is, p_ni_inv,
                                         HCU[layer], HCI[layer],
                                         (uint4*)p_pu, (uint4*)p_pi);
        } else {
            phaseB_last<<<ALL_BLKS, TB>>>((const uint4*)p_ai, (const uint4*)p_au,
                                          p_rp_u, p_cols_u, p_rp_i, p_cols_i,
                                          p_nu_is, p_ni_is,
                                          (const float4*)user_emb, (const float4*)item_emb,
                                          (const uint4*)p_hcu0, (const uint4*)p_hcu1,
                                          (const uint4*)p_hci0, (const uint4*)p_hci1,
                                          (float4*)sum_u, (float4*)sum_i);
        }
    }
}